// round 15
// baseline (speedup 1.0000x reference)
#include <cuda_runtime.h>
#include <cuda_fp16.h>
#include <cstdint>

#define Z_STRIDE 528                      // 256 fp16 + 16B pad -> conflict-free ldmatrix
#define SMEM_TOTAL (256 * Z_STRIDE)       // 135168 B, 1 CTA/SM

__device__ uint32_t g_wfrag[32768];       // A fragments: [wb(8)][lane(32)][fi(128)]

__device__ __forceinline__ uint32_t s2u(const void* p){
    uint32_t a;
    asm("{ .reg .u64 t; cvta.to.shared.u64 t, %1; cvt.u32.u64 %0, t; }" : "=r"(a) : "l"(p));
    return a;
}

// ---------------- weight prep (A fragments for mma.sync) ----------------
__global__ void __launch_bounds__(256) prep_weights(const float* __restrict__ cw){
    const int idx = blockIdx.x * 256 + threadIdx.x;      // 32768
    int wb = idx >> 12;
    int ln = (idx >> 7) & 31;
    int fi = idx & 127;
    int kt = fi >> 3, mt = (fi >> 2) & 1, j = fi & 3;
    int o = wb * 32 + mt * 16 + (ln >> 2) + (j & 1) * 8;
    int c = kt * 16 + (ln & 3) * 2 + (j >> 1) * 8;
    float2 wv = *(const float2*)(cw + o * 256 + c);
    __half2 hw = __floats2half2_rn(wv.x, wv.y);
    g_wfrag[idx] = *(uint32_t*)&hw;
}

// ---------------- fused kernel: one 512-thread CTA per (b, h) ----------------
// LN uses all 16 warps (16 rows each); GEMM uses warps 0-7 in R7's exact shape.
__global__ void __launch_bounds__(512, 1)
fused_ln_conv_relu(const float* __restrict__ x, const float* __restrict__ y,
                   const float* __restrict__ lnw, const float* __restrict__ lnb,
                   float* __restrict__ out)
{
    extern __shared__ __align__(128) char smem[];
    const uint32_t su = s2u(smem);
    const int tid = threadIdx.x, wid = tid >> 5, lane = tid & 31;
    const int b = blockIdx.x >> 8, h = blockIdx.x & 255;
    const size_t base_bh = ((size_t)b << 24) + ((size_t)h << 8);

    // ---- phase 1: residual add + LayerNorm -> Z fp16 [256c][256w], 16 rows/warp ----
    {
        const float4 lwa = *(const float4*)(lnw + 4 * lane);
        const float4 lwb = *(const float4*)(lnw + 128 + 4 * lane);
        const float4 lba = *(const float4*)(lnb + 4 * lane);
        const float4 lbb = *(const float4*)(lnb + 128 + 4 * lane);
        #pragma unroll 4
        for (int r = 0; r < 16; r++) {
            const int c = wid * 16 + r;
            const float* px = x + base_bh + ((size_t)c << 16) + 4 * lane;
            const float* py = y + base_bh + ((size_t)c << 16) + 4 * lane;
            float4 xa = *(const float4*)px;
            float4 xb = *(const float4*)(px + 128);
            float4 ya = *(const float4*)py;
            float4 yb = *(const float4*)(py + 128);
            float v0 = xa.x + ya.x, v1 = xa.y + ya.y, v2 = xa.z + ya.z, v3 = xa.w + ya.w;
            float v4 = xb.x + yb.x, v5 = xb.y + yb.y, v6 = xb.z + yb.z, v7 = xb.w + yb.w;
            float s = v0+v1+v2+v3+v4+v5+v6+v7;
            float q = v0*v0+v1*v1+v2*v2+v3*v3+v4*v4+v5*v5+v6*v6+v7*v7;
            #pragma unroll
            for (int o_ = 16; o_; o_ >>= 1) {
                s += __shfl_xor_sync(0xFFFFFFFFu, s, o_);
                q += __shfl_xor_sync(0xFFFFFFFFu, q, o_);
            }
            const float mean = s * (1.0f / 256.0f);
            const float rstd = rsqrtf(q * (1.0f / 256.0f) - mean * mean + 1e-5f);
            __half2 h01 = __floats2half2_rn((v0-mean)*rstd*lwa.x + lba.x, (v1-mean)*rstd*lwa.y + lba.y);
            __half2 h23 = __floats2half2_rn((v2-mean)*rstd*lwa.z + lba.z, (v3-mean)*rstd*lwa.w + lba.w);
            __half2 h45 = __floats2half2_rn((v4-mean)*rstd*lwb.x + lbb.x, (v5-mean)*rstd*lwb.y + lbb.y);
            __half2 h67 = __floats2half2_rn((v6-mean)*rstd*lwb.z + lbb.z, (v7-mean)*rstd*lwb.w + lbb.w);
            char* zr = smem + c * Z_STRIDE;
            *(uint2*)(zr + 8 * lane)       = make_uint2(*(uint32_t*)&h01, *(uint32_t*)&h23);
            *(uint2*)(zr + 256 + 8 * lane) = make_uint2(*(uint32_t*)&h45, *(uint32_t*)&h67);
        }
    }
    __syncthreads();

    // ---- phase 2 (warps 0-7 only): GEMM, R7's exact shape ----
    if (wid >= 8) return;                 // helper warps done; free their slots

    const uint4* wf = (const uint4*)g_wfrag + ((wid * 32 + lane) * 32);
    const int g = lane >> 2, t = lane & 3;
    const uint32_t krow_off = ((uint32_t)((lane >> 3) & 1)) * 8 + (lane & 7);
    const uint32_t ncol_off = ((uint32_t)(lane >> 4)) * 8;
    const int o_row = wid * 32 + g;
    float* outp = out + ((size_t)b << 24) + ((size_t)o_row << 16) + ((size_t)h << 8);

    #pragma unroll 1
    for (int wc = 0; wc < 4; wc++) {                 // w-chunks of 64
        float acc[2][8][4] = {};
        #pragma unroll 2
        for (int kt = 0; kt < 16; kt++) {
            uint4 a0 = __ldg(wf + kt * 2);
            uint4 a1 = __ldg(wf + kt * 2 + 1);
            uint32_t bf[8][2];
            #pragma unroll
            for (int qq = 0; qq < 4; qq++) {
                uint32_t addr = su + (kt * 16 + krow_off) * Z_STRIDE
                                   + (uint32_t)(wc * 64 + qq * 16) * 2 + ncol_off * 2;
                asm volatile("ldmatrix.sync.aligned.m8n8.x4.trans.shared.b16 {%0,%1,%2,%3}, [%4];"
                             : "=r"(bf[2*qq][0]), "=r"(bf[2*qq][1]),
                               "=r"(bf[2*qq+1][0]), "=r"(bf[2*qq+1][1])
                             : "r"(addr));
            }
            #pragma unroll
            for (int nt = 0; nt < 8; nt++) {
                asm volatile(
                    "mma.sync.aligned.m16n8k16.row.col.f32.f16.f16.f32 "
                    "{%0,%1,%2,%3}, {%4,%5,%6,%7}, {%8,%9}, {%0,%1,%2,%3};"
                    : "+f"(acc[0][nt][0]), "+f"(acc[0][nt][1]), "+f"(acc[0][nt][2]), "+f"(acc[0][nt][3])
                    : "r"(a0.x), "r"(a0.y), "r"(a0.z), "r"(a0.w),
                      "r"(bf[nt][0]), "r"(bf[nt][1]));
                asm volatile(
                    "mma.sync.aligned.m16n8k16.row.col.f32.f16.f16.f32 "
                    "{%0,%1,%2,%3}, {%4,%5,%6,%7}, {%8,%9}, {%0,%1,%2,%3};"
                    : "+f"(acc[1][nt][0]), "+f"(acc[1][nt][1]), "+f"(acc[1][nt][2]), "+f"(acc[1][nt][3])
                    : "r"(a1.x), "r"(a1.y), "r"(a1.z), "r"(a1.w),
                      "r"(bf[nt][0]), "r"(bf[nt][1]));
            }
        }
        // store this w-chunk with ReLU, direct from fragments (streaming)
        #pragma unroll
        for (int mt = 0; mt < 2; mt++) {
            #pragma unroll
            for (int nt = 0; nt < 8; nt++) {
                const int w = wc * 64 + nt * 8 + t * 2;
                float* p0 = outp + ((size_t)(mt * 16) << 16) + w;
                float2 v0 = make_float2(fmaxf(acc[mt][nt][0], 0.f), fmaxf(acc[mt][nt][1], 0.f));
                float2 v1 = make_float2(fmaxf(acc[mt][nt][2], 0.f), fmaxf(acc[mt][nt][3], 0.f));
                __stcs((float2*)p0, v0);
                __stcs((float2*)(p0 + (8 << 16)), v1);   // +8 o-rows
            }
        }
    }
}

extern "C" void kernel_launch(void* const* d_in, const int* in_sizes, int n_in,
                              void* d_out, int out_size) {
    (void)in_sizes; (void)n_in; (void)out_size;
    const float* x   = (const float*)d_in[0];
    const float* y   = (const float*)d_in[1];
    const float* lnw = (const float*)d_in[2];
    const float* lnb = (const float*)d_in[3];
    const float* cw  = (const float*)d_in[4];
    float* out = (float*)d_out;

    cudaFuncSetAttribute(fused_ln_conv_relu, cudaFuncAttributeMaxDynamicSharedMemorySize, SMEM_TOTAL);

    prep_weights<<<128, 256>>>(cw);
    fused_ln_conv_relu<<<1024, 512, SMEM_TOTAL>>>(x, y, lnw, lnb, out);
}

// round 16
// speedup vs baseline: 1.1532x; 1.1532x over previous
#include <cuda_runtime.h>
#include <cuda_fp16.h>
#include <cstdint>

#define Z_STRIDE 528                      // 256 fp16 + 16B pad -> conflict-free ldmatrix
#define Z_BYTES  (256 * Z_STRIDE)         // 135168
#define OFF_RING Z_BYTES                  // A ring: [wid(8)][slot(4)][lane(32)][32B] = 32 KB
#define SMEM_TOTAL (Z_BYTES + 32768)      // 167936 B, 1 CTA/SM

__device__ uint32_t g_wkt[32768];         // A fragments kt-major: [kt(16)][mb(8)][lane(32)][8 u32]

__device__ __forceinline__ uint32_t s2u(const void* p){
    uint32_t a;
    asm("{ .reg .u64 t; cvta.to.shared.u64 t, %1; cvt.u32.u64 %0, t; }" : "=r"(a) : "l"(p));
    return a;
}

// ---------------- weight prep (A fragments, kt-major for cp.async streaming) ----------------
__global__ void __launch_bounds__(256) prep_weights(const float* __restrict__ cw){
    const int idx = blockIdx.x * 256 + threadIdx.x;      // 32768
    int wb = idx >> 12;
    int ln = (idx >> 7) & 31;
    int fi = idx & 127;
    int kt = fi >> 3, mt = (fi >> 2) & 1, j = fi & 3;
    int o = wb * 32 + mt * 16 + (ln >> 2) + (j & 1) * 8;
    int c = kt * 16 + (ln & 3) * 2 + (j >> 1) * 8;
    float2 wv = *(const float2*)(cw + o * 256 + c);
    __half2 hw = __floats2half2_rn(wv.x, wv.y);
    g_wkt[(((kt * 8 + wb) * 32 + ln) << 3) + mt * 4 + j] = *(uint32_t*)&hw;
}

// ---------------- fused kernel: one 256-thread CTA per (b, h) ----------------
__global__ void __launch_bounds__(256, 1)
fused_ln_conv_relu(const float* __restrict__ x, const float* __restrict__ y,
                   const float* __restrict__ lnw, const float* __restrict__ lnb,
                   float* __restrict__ out)
{
    extern __shared__ __align__(128) char smem[];
    const uint32_t su = s2u(smem);
    const int tid = threadIdx.x, wid = tid >> 5, lane = tid & 31;
    const int b = blockIdx.x >> 8, h = blockIdx.x & 255;
    const size_t base_bh = ((size_t)b << 24) + ((size_t)h << 8);

    const float4 lwa = *(const float4*)(lnw + 4 * lane);
    const float4 lwb = *(const float4*)(lnw + 128 + 4 * lane);
    const float4 lba = *(const float4*)(lnb + 4 * lane);
    const float4 lbb = *(const float4*)(lnb + 128 + 4 * lane);

    // ---- phase 1: residual add + LayerNorm -> Z fp16 [256c][256w] (R7's exact code) ----
    {
        #pragma unroll 2
        for (int r = 0; r < 32; r++) {
            const int c = wid * 32 + r;
            const float* px = x + base_bh + ((size_t)c << 16) + 4 * lane;
            const float* py = y + base_bh + ((size_t)c << 16) + 4 * lane;
            float4 xa = *(const float4*)px;
            float4 xb = *(const float4*)(px + 128);
            float4 ya = *(const float4*)py;
            float4 yb = *(const float4*)(py + 128);
            float v0 = xa.x + ya.x, v1 = xa.y + ya.y, v2 = xa.z + ya.z, v3 = xa.w + ya.w;
            float v4 = xb.x + yb.x, v5 = xb.y + yb.y, v6 = xb.z + yb.z, v7 = xb.w + yb.w;
            float s = v0+v1+v2+v3+v4+v5+v6+v7;
            float q = v0*v0+v1*v1+v2*v2+v3*v3+v4*v4+v5*v5+v6*v6+v7*v7;
            #pragma unroll
            for (int o_ = 16; o_; o_ >>= 1) {
                s += __shfl_xor_sync(0xFFFFFFFFu, s, o_);
                q += __shfl_xor_sync(0xFFFFFFFFu, q, o_);
            }
            const float mean = s * (1.0f / 256.0f);
            const float rstd = rsqrtf(q * (1.0f / 256.0f) - mean * mean + 1e-5f);
            __half2 h01 = __floats2half2_rn((v0-mean)*rstd*lwa.x + lba.x, (v1-mean)*rstd*lwa.y + lba.y);
            __half2 h23 = __floats2half2_rn((v2-mean)*rstd*lwa.z + lba.z, (v3-mean)*rstd*lwa.w + lba.w);
            __half2 h45 = __floats2half2_rn((v4-mean)*rstd*lwb.x + lbb.x, (v5-mean)*rstd*lwb.y + lbb.y);
            __half2 h67 = __floats2half2_rn((v6-mean)*rstd*lwb.z + lbb.z, (v7-mean)*rstd*lwb.w + lbb.w);
            char* zr = smem + c * Z_STRIDE;
            *(uint2*)(zr + 8 * lane)       = make_uint2(*(uint32_t*)&h01, *(uint32_t*)&h23);
            *(uint2*)(zr + 256 + 8 * lane) = make_uint2(*(uint32_t*)&h45, *(uint32_t*)&h67);
        }
    }
    __syncthreads();

    // ---- phase 2: GEMM, R7 shape; A streamed via warp-private cp.async smem ring ----
    const int g = lane >> 2, t = lane & 3;
    const uint32_t krow_off = ((uint32_t)((lane >> 3) & 1)) * 8 + (lane & 7);
    const uint32_t ncol_off = ((uint32_t)(lane >> 4)) * 8;
    const int o_row = wid * 32 + g;
    float* outp = out + ((size_t)b << 24) + ((size_t)o_row << 16) + ((size_t)h << 8);

    // ring addressing: this lane's 32B within [wid][slot]
    const uint32_t ring_lane = su + OFF_RING + (uint32_t)(wid * 4) * 1024 + (uint32_t)lane * 32;
    const char* wsrc_lane = (const char*)g_wkt + (size_t)wid * 1024 + (size_t)lane * 32;

    // fill for global stream index f (slice kt = f&15 of W, slot = f&3)
    #define AFILL(f_) do {                                                              \
        uint32_t dst = ring_lane + (uint32_t)((f_) & 3) * 1024;                         \
        const char* src = wsrc_lane + (size_t)((f_) & 15) * 8192;                       \
        asm volatile("cp.async.cg.shared.global [%0], [%1], 16;" :: "r"(dst), "l"(src)); \
        asm volatile("cp.async.cg.shared.global [%0], [%1], 16;"                        \
                     :: "r"(dst + 16), "l"(src + 16));                                  \
        asm volatile("cp.async.commit_group;" ::: "memory");                            \
    } while (0)

    AFILL(0); AFILL(1); AFILL(2);

    #pragma unroll 1
    for (int wc = 0; wc < 4; wc++) {                 // w-chunks of 64
        float acc[2][8][4] = {};
        #pragma unroll 2
        for (int kt = 0; kt < 16; kt++) {
            const int i = wc * 16 + kt;              // global stream index 0..63
            if (i < 61) { asm volatile("cp.async.wait_group 2;" ::: "memory"); }
            else        { asm volatile("cp.async.wait_group 0;" ::: "memory"); }

            // A fragments from ring slot (LDS.128 x2, lane reads its own bytes)
            uint4 a0, a1;
            {
                uint32_t ab = ring_lane + (uint32_t)(i & 3) * 1024;
                asm volatile("ld.shared.v4.u32 {%0,%1,%2,%3}, [%4];"
                             : "=r"(a0.x), "=r"(a0.y), "=r"(a0.z), "=r"(a0.w) : "r"(ab));
                asm volatile("ld.shared.v4.u32 {%0,%1,%2,%3}, [%4];"
                             : "=r"(a1.x), "=r"(a1.y), "=r"(a1.z), "=r"(a1.w) : "r"(ab + 16));
            }
            uint32_t bf[8][2];
            #pragma unroll
            for (int qq = 0; qq < 4; qq++) {
                uint32_t addr = su + (kt * 16 + krow_off) * Z_STRIDE
                                   + (uint32_t)(wc * 64 + qq * 16) * 2 + ncol_off * 2;
                asm volatile("ldmatrix.sync.aligned.m8n8.x4.trans.shared.b16 {%0,%1,%2,%3}, [%4];"
                             : "=r"(bf[2*qq][0]), "=r"(bf[2*qq][1]),
                               "=r"(bf[2*qq+1][0]), "=r"(bf[2*qq+1][1])
                             : "r"(addr));
            }
            // prefetch slice i+3 into the slot freed at i-1
            if (i < 61) AFILL(i + 3);

            #pragma unroll
            for (int nt = 0; nt < 8; nt++) {
                asm volatile(
                    "mma.sync.aligned.m16n8k16.row.col.f32.f16.f16.f32 "
                    "{%0,%1,%2,%3}, {%4,%5,%6,%7}, {%8,%9}, {%0,%1,%2,%3};"
                    : "+f"(acc[0][nt][0]), "+f"(acc[0][nt][1]), "+f"(acc[0][nt][2]), "+f"(acc[0][nt][3])
                    : "r"(a0.x), "r"(a0.y), "r"(a0.z), "r"(a0.w),
                      "r"(bf[nt][0]), "r"(bf[nt][1]));
                asm volatile(
                    "mma.sync.aligned.m16n8k16.row.col.f32.f16.f16.f32 "
                    "{%0,%1,%2,%3}, {%4,%5,%6,%7}, {%8,%9}, {%0,%1,%2,%3};"
                    : "+f"(acc[1][nt][0]), "+f"(acc[1][nt][1]), "+f"(acc[1][nt][2]), "+f"(acc[1][nt][3])
                    : "r"(a1.x), "r"(a1.y), "r"(a1.z), "r"(a1.w),
                      "r"(bf[nt][0]), "r"(bf[nt][1]));
            }
        }
        // store this w-chunk with ReLU, direct from fragments (streaming)
        #pragma unroll
        for (int mt = 0; mt < 2; mt++) {
            #pragma unroll
            for (int nt = 0; nt < 8; nt++) {
                const int w = wc * 64 + nt * 8 + t * 2;
                float* p0 = outp + ((size_t)(mt * 16) << 16) + w;
                float2 v0 = make_float2(fmaxf(acc[mt][nt][0], 0.f), fmaxf(acc[mt][nt][1], 0.f));
                float2 v1 = make_float2(fmaxf(acc[mt][nt][2], 0.f), fmaxf(acc[mt][nt][3], 0.f));
                __stcs((float2*)p0, v0);
                __stcs((float2*)(p0 + (8 << 16)), v1);   // +8 o-rows
            }
        }
    }
    #undef AFILL
}

extern "C" void kernel_launch(void* const* d_in, const int* in_sizes, int n_in,
                              void* d_out, int out_size) {
    (void)in_sizes; (void)n_in; (void)out_size;
    const float* x   = (const float*)d_in[0];
    const float* y   = (const float*)d_in[1];
    const float* lnw = (const float*)d_in[2];
    const float* lnb = (const float*)d_in[3];
    const float* cw  = (const float*)d_in[4];
    float* out = (float*)d_out;

    cudaFuncSetAttribute(fused_ln_conv_relu, cudaFuncAttributeMaxDynamicSharedMemorySize, SMEM_TOTAL);

    prep_weights<<<128, 256>>>(cw);
    fused_ln_conv_relu<<<1024, 256, SMEM_TOTAL>>>(x, y, lnw, lnb, out);
}